// round 16
// baseline (speedup 1.0000x reference)
#include <cuda_runtime.h>
#include <cuda_bf16.h>
#include <math.h>
#include <cstdint>

#define BB   4
#define NPTS 16384
#define MPTS 4096
#define C1   128
#define C2   256
#define HCH  256
#define K1   384
#define NTOT (BB*NPTS)   // 65536
#define HALF (NTOT/2)

typedef unsigned long long u64;

// ---------------- mma / ldmatrix / cp.async helpers (sm_80+ baseline PTX) ----------------
__device__ __forceinline__ uint32_t smem_u32(const void* p) {
    uint32_t a;
    asm("{ .reg .u64 t; cvta.to.shared.u64 t, %1; cvt.u32.u64 %0, t; }" : "=r"(a) : "l"(p));
    return a;
}
__device__ __forceinline__ void ldsm4(uint32_t* r, uint32_t addr) {
    asm volatile("ldmatrix.sync.aligned.m8n8.x4.shared.b16 {%0,%1,%2,%3}, [%4];"
        : "=r"(r[0]), "=r"(r[1]), "=r"(r[2]), "=r"(r[3]) : "r"(addr));
}
__device__ __forceinline__ void mma_bf16(float* d, const uint32_t* a, const uint32_t* b) {
    asm volatile("mma.sync.aligned.m16n8k16.row.col.f32.bf16.bf16.f32 "
        "{%0,%1,%2,%3}, {%4,%5,%6,%7}, {%8,%9}, {%0,%1,%2,%3};"
        : "+f"(d[0]), "+f"(d[1]), "+f"(d[2]), "+f"(d[3])
        : "r"(a[0]), "r"(a[1]), "r"(a[2]), "r"(a[3]), "r"(b[0]), "r"(b[1]));
}
__device__ __forceinline__ void cp16(uint32_t saddr, const void* gaddr) {
    asm volatile("cp.async.cg.shared.global [%0], [%1], 16;" :: "r"(saddr), "l"(gaddr));
}
#define CP_COMMIT() asm volatile("cp.async.commit_group;" ::: "memory")
#define CP_WAIT(n)  asm volatile("cp.async.wait_group %0;" :: "n"(n) : "memory")

// smem stage layout: Ah, Al, Bh, Bl each 128 rows x 40 bf16 (80B rows)
#define MAT_BYTES (128*80)
#define OFF_AH 0
#define OFF_AL (MAT_BYTES)
#define OFF_BH (2*MAT_BYTES)
#define OFF_BL (3*MAT_BYTES)
#define STAGE  (4*MAT_BYTES)     // 40960
#define SM_TOT (2*STAGE)         // 81920
#define BS_OFF (SM_TOT - 2048)   // stats scratch; MODE1 transpose buffer (33.8KB) < BS_OFF

// ---------------- scratch (device globals) ----------------
__device__ float g_kfT[(size_t)BB*MPTS*C2];                         // 16.8 MB point-major known feats
__device__ __align__(16) __nv_bfloat16 g_ah[(size_t)NTOT*K1];       // A1 hi (point-major)
__device__ __align__(16) __nv_bfloat16 g_al[(size_t)NTOT*K1];       // A1 lo
__device__ __align__(16) __nv_bfloat16 g_w1h[HCH*K1], g_w1l[HCH*K1];
__device__ __align__(16) __nv_bfloat16 g_w2h[HCH*HCH], g_w2l[HCH*HCH];
__device__ __align__(16) __nv_bfloat16 g_a2h[(size_t)NTOT*HCH];     // A2 hi
__device__ __align__(16) __nv_bfloat16 g_a2l[(size_t)NTOT*HCH];
__device__ float g_y1[(size_t)NTOT*HCH];                            // gemm1 out, point-major
__device__ float g_ps[NTOT*12];
__device__ int   g_pi[NTOT*12];
__device__ float g_sum1[HCH], g_sq1[HCH], g_scale1[HCH], g_shift1[HCH];
__device__ float g_sum2[HCH], g_sq2[HCH], g_scale2[HCH], g_shift2[HCH];

__device__ __forceinline__ void bsplit(float x, __nv_bfloat16& h, __nv_bfloat16& l) {
    h = __float2bfloat16_rn(x);
    l = __float2bfloat16_rn(x - __bfloat162float(h));
}

// ---------------- prep A: kf transpose + W1/W2 split + zero stats ----------------
__global__ void prep_kfw_kernel(const float* __restrict__ kf,
                                const float* __restrict__ W1,
                                const float* __restrict__ W2) {
    __shared__ float tile[32][33];
    int tx = threadIdx.x, ty = threadIdx.y;
    int b = blockIdx.z, y = blockIdx.y, x = blockIdx.x;
    int tid = ty * 32 + tx;

    if (y < 8) {                                     // kf [b][c][p] -> g_kfT [b][p][c]
        int p0 = x * 32, c0 = y * 32;
        const float* src = kf + (size_t)b * C2 * MPTS;
        float* dst = g_kfT + (size_t)b * MPTS * C2;
#pragma unroll
        for (int r = 0; r < 32; r += 8)
            tile[ty + r][tx] = src[(size_t)(c0 + ty + r) * MPTS + p0 + tx];
        __syncthreads();
#pragma unroll
        for (int r = 0; r < 32; r += 8)
            dst[(size_t)(p0 + ty + r) * C2 + c0 + tx] = tile[tx][ty + r];
    } else if (y == 8) {                             // W1 split
        if (b != 0) return;
#pragma unroll
        for (int c = 0; c < 3; c++) {
            int i = (x * 3 + c) * 256 + tid;
            __nv_bfloat16 h, l; bsplit(W1[i], h, l);
            g_w1h[i] = h; g_w1l[i] = l;
        }
    } else {                                         // y == 9: W2 split + stats
        if (b != 0) return;
        if (x < 64) {
#pragma unroll
            for (int c = 0; c < 4; c++) {
                int i = (x * 4 + c) * 256 + tid;
                __nv_bfloat16 h, l; bsplit(W2[i], h, l);
                g_w2h[i] = h; g_w2l[i] = l;
            }
        } else if (x == 64) {
            g_sum1[tid] = 0.f; g_sq1[tid] = 0.f;
            g_sum2[tid] = 0.f; g_sq2[tid] = 0.f;
        }
    }
}

// ---------------- prep B: uf transpose + bf16 split -> g_ah/g_al[j][256+c] ----------------
__global__ void prep_uf_kernel(const float* __restrict__ uf) {
    __shared__ float tile[32][33];
    int tx = threadIdx.x, ty = threadIdx.y;
    int b = blockIdx.z;
    int c0 = blockIdx.y * 32, i0 = blockIdx.x * 32;
    const float* src = uf + (size_t)b * C1 * NPTS;
#pragma unroll
    for (int r = 0; r < 32; r += 8)
        tile[ty + r][tx] = src[(size_t)(c0 + ty + r) * NPTS + i0 + tx];
    __syncthreads();
#pragma unroll
    for (int r = 0; r < 32; r += 8) {
        int j = b * NPTS + i0 + ty + r;
        float v = tile[tx][ty + r];
        __nv_bfloat16 h, l; bsplit(v, h, l);
        g_ah[(size_t)j * K1 + C2 + c0 + tx] = h;
        g_al[(size_t)j * K1 + C2 + c0 + tx] = l;
    }
}

// ---------------- 4-way split-m 3-NN partials, 2 points per thread, j-range offset ----------------
__global__ void __launch_bounds__(128) three_nn_partial_kernel(
        const float* __restrict__ unknown, const float* __restrict__ known, int jbase) {
    int tid = threadIdx.x;
    int gA = jbase + blockIdx.x * 256 + tid;
    int gB = gA + 128;
    int t = blockIdx.y;                              // 0..3
    int b = gA >> 14;

    __shared__ float4 sk[1024];
    const float* kb = known + ((size_t)b * MPTS + t * 1024) * 3;
    for (int q = tid; q < 1024; q += 128) {
        float x = kb[q*3+0], y = kb[q*3+1], z = kb[q*3+2];
        sk[q] = make_float4(x, y, z, x*x + y*y + z*z);
    }
    __syncthreads();

    float ax = unknown[gA*3+0], ay = unknown[gA*3+1], az = unknown[gA*3+2];
    float bx = unknown[gB*3+0], by = unknown[gB*3+1], bz = unknown[gB*3+2];
    float caA = -2.f*ax, cbA = -2.f*ay, ccA = -2.f*az;
    float caB = -2.f*bx, cbB = -2.f*by, ccB = -2.f*bz;

    float a0 = 3.4e38f, a1 = 3.4e38f, a2 = 3.4e38f;
    float b0 = 3.4e38f, b1 = 3.4e38f, b2 = 3.4e38f;
    int   ia0 = 0, ia1 = 0, ia2 = 0, ib0 = 0, ib1 = 0, ib2 = 0;

#pragma unroll 4
    for (int jj = 0; jj < 1024; jj++) {
        float4 k4 = sk[jj];
        float s = fmaf(k4.x, caA, fmaf(k4.y, cbA, fmaf(k4.z, ccA, k4.w)));
        float u = fmaf(k4.x, caB, fmaf(k4.y, cbB, fmaf(k4.z, ccB, k4.w)));
        if (s < a2) {
            if (s < a1) {
                a2 = a1; ia2 = ia1;
                if (s < a0) { a1 = a0; ia1 = ia0; a0 = s; ia0 = jj; }
                else        { a1 = s;  ia1 = jj; }
            } else { a2 = s; ia2 = jj; }
        }
        if (u < b2) {
            if (u < b1) {
                b2 = b1; ib2 = ib1;
                if (u < b0) { b1 = b0; ib1 = ib0; b0 = u; ib0 = jj; }
                else        { b1 = u;  ib1 = jj; }
            } else { b2 = u; ib2 = jj; }
        }
    }
    int base = t * 1024;
    int oA = gA * 12 + t * 3, oB = gB * 12 + t * 3;
    g_ps[oA+0] = a0; g_ps[oA+1] = a1; g_ps[oA+2] = a2;
    g_pi[oA+0] = base + ia0; g_pi[oA+1] = base + ia1; g_pi[oA+2] = base + ia2;
    g_ps[oB+0] = b0; g_ps[oB+1] = b1; g_ps[oB+2] = b2;
    g_pi[oB+0] = base + ib0; g_pi[oB+1] = base + ib1; g_pi[oB+2] = base + ib2;
}

// ---------------- merge + gather + interpolate -> A[j][0..255] bf16 hi/lo, j-range offset ----------------
__global__ void __launch_bounds__(256) interp_bf16_kernel(const float* __restrict__ unknown, int jbase) {
    int warp = threadIdx.x >> 5, lane = threadIdx.x & 31;
    int g = jbase + blockIdx.x * 8 + warp;
    int b = g >> 14;

    float sl = (lane < 12) ? g_ps[g*12 + lane] : 3.4e38f;
    int   il = (lane < 12) ? g_pi[g*12 + lane] : 0;
    float s0 = 3.4e38f, s1 = 3.4e38f, s2 = 3.4e38f;
    int   i0 = 0, i1 = 0, i2 = 0;
#pragma unroll
    for (int j = 0; j < 12; j++) {
        float sj = __shfl_sync(0xffffffffu, sl, j);
        int   ij = __shfl_sync(0xffffffffu, il, j);
        if (sj < s2) {
            if (sj < s1) {
                s2 = s1; i2 = i1;
                if (sj < s0) { s1 = s0; i1 = i0; s0 = sj; i0 = ij; }
                else         { s1 = sj; i1 = ij; }
            } else { s2 = sj; i2 = ij; }
        }
    }
    float ux = unknown[g*3+0], uy = unknown[g*3+1], uz = unknown[g*3+2];
    float u2 = ux*ux + uy*uy + uz*uz;
    float d0 = s0 + u2, d1 = s1 + u2, d2 = s2 + u2;
    float r0 = 1.f / (d0 + 1e-8f), r1 = 1.f / (d1 + 1e-8f), r2 = 1.f / (d2 + 1e-8f);
    float rs = r0 + r1 + r2;
    float w0 = r0 / rs, w1 = r1 / rs, w2 = r2 / rs;

    const float4* f0 = (const float4*)&g_kfT[((size_t)(b*MPTS) + i0) * C2];
    const float4* f1 = (const float4*)&g_kfT[((size_t)(b*MPTS) + i1) * C2];
    const float4* f2 = (const float4*)&g_kfT[((size_t)(b*MPTS) + i2) * C2];

    float vals[8];
#pragma unroll
    for (int h = 0; h < 2; h++) {
        int v = lane*2 + h;
        float4 a = f0[v], c = f1[v], d = f2[v];
        vals[h*4+0] = fmaf(w0, a.x, fmaf(w1, c.x, w2 * d.x));
        vals[h*4+1] = fmaf(w0, a.y, fmaf(w1, c.y, w2 * d.y));
        vals[h*4+2] = fmaf(w0, a.z, fmaf(w1, c.z, w2 * d.z));
        vals[h*4+3] = fmaf(w0, a.w, fmaf(w1, c.w, w2 * d.w));
    }
    uint4 uh, ul;
    uint32_t* ph = (uint32_t*)&uh;
    uint32_t* pl = (uint32_t*)&ul;
#pragma unroll
    for (int q = 0; q < 4; q++) {
        __nv_bfloat16 h0, l0, h1, l1;
        bsplit(vals[q*2+0], h0, l0);
        bsplit(vals[q*2+1], h1, l1);
        __nv_bfloat162 hh = __nv_bfloat162(h0, h1);
        __nv_bfloat162 ll = __nv_bfloat162(l0, l1);
        ph[q] = *(uint32_t*)&hh;
        pl[q] = *(uint32_t*)&ll;
    }
    *(uint4*)(g_ah + (size_t)g * K1 + lane * 8) = uh;
    *(uint4*)(g_al + (size_t)g * K1 + lane * 8) = ul;
}

// ---------------- bf16x3 GEMM via mma.sync (R8 schedule, fused stats) ----------------
template<int KD, int MODE>
__global__ void __launch_bounds__(256, 2) gemm_tc_kernel(float* __restrict__ outp) {
    extern __shared__ __align__(16) char smem[];
    const uint32_t su = smem_u32(smem);
    const int tid = threadIdx.x, lane = tid & 31, warp = tid >> 5;
    const int warp_m = warp >> 1, warp_n = warp & 1;
    const int j0 = blockIdx.x * 128, o0 = blockIdx.y * 128;

    const __nv_bfloat16 *Ah, *Al, *Bh, *Bl;
    if (MODE == 0) { Ah = g_ah;  Al = g_al;  Bh = g_w1h; Bl = g_w1l; }
    else           { Ah = g_a2h; Al = g_a2l; Bh = g_w2h; Bl = g_w2l; }

    const int NCH = KD / 32;
    int lrow0 = tid >> 2, lcg = (tid & 3) * 8;

    uint32_t a_off[2], b_off[4];
#pragma unroll
    for (int mt = 0; mt < 2; mt++)
        a_off[mt] = (uint32_t)((warp_m*32 + mt*16 + (lane & 15)) * 80 + ((lane >> 4) << 3) * 2);
#pragma unroll
    for (int np = 0; np < 4; np++)
        b_off[np] = (uint32_t)((warp_n*64 + np*16 + (lane & 7) + ((lane >> 4) << 3)) * 80
                               + (((lane >> 3) & 1) << 3) * 2);

    float acc[2][8][4];
#pragma unroll
    for (int mt = 0; mt < 2; mt++)
#pragma unroll
        for (int nt = 0; nt < 8; nt++)
#pragma unroll
            for (int q = 0; q < 4; q++) acc[mt][nt][q] = 0.f;

    // prefetch chunk 0
    {
        uint32_t sb = su;
#pragma unroll
        for (int t = 0; t < 2; t++) {
            int row = lrow0 + t * 64;
            uint32_t so = (uint32_t)(row * 80 + lcg * 2);
            cp16(sb + OFF_AH + so, Ah + (size_t)(j0 + row) * KD + lcg);
            cp16(sb + OFF_AL + so, Al + (size_t)(j0 + row) * KD + lcg);
            cp16(sb + OFF_BH + so, Bh + (size_t)(o0 + row) * KD + lcg);
            cp16(sb + OFF_BL + so, Bl + (size_t)(o0 + row) * KD + lcg);
        }
        CP_COMMIT();
    }

    for (int ch = 0; ch < NCH; ch++) {
        if (ch + 1 < NCH) {
            int kc = (ch + 1) * 32;
            uint32_t sb = su + ((ch + 1) & 1) * STAGE;
#pragma unroll
            for (int t = 0; t < 2; t++) {
                int row = lrow0 + t * 64;
                uint32_t so = (uint32_t)(row * 80 + lcg * 2);
                cp16(sb + OFF_AH + so, Ah + (size_t)(j0 + row) * KD + kc + lcg);
                cp16(sb + OFF_AL + so, Al + (size_t)(j0 + row) * KD + kc + lcg);
                cp16(sb + OFF_BH + so, Bh + (size_t)(o0 + row) * KD + kc + lcg);
                cp16(sb + OFF_BL + so, Bl + (size_t)(o0 + row) * KD + kc + lcg);
            }
            CP_COMMIT();
            CP_WAIT(1);
        } else {
            CP_WAIT(0);
        }
        __syncthreads();

        uint32_t sb = su + (ch & 1) * STAGE;
#pragma unroll
        for (int ks = 0; ks < 32; ks += 16) {
            uint32_t Ahf[2][4], Alf[2][4], Bhf[4][4], Blf[4][4];
#pragma unroll
            for (int mt = 0; mt < 2; mt++) {
                ldsm4(Ahf[mt], sb + OFF_AH + a_off[mt] + ks*2);
                ldsm4(Alf[mt], sb + OFF_AL + a_off[mt] + ks*2);
            }
#pragma unroll
            for (int np = 0; np < 4; np++)
                ldsm4(Bhf[np], sb + OFF_BH + b_off[np] + ks*2);
#pragma unroll
            for (int np = 0; np < 4; np++)
                ldsm4(Blf[np], sb + OFF_BL + b_off[np] + ks*2);
#pragma unroll
            for (int mt = 0; mt < 2; mt++)
#pragma unroll
                for (int nt = 0; nt < 8; nt++)
                    mma_bf16(acc[mt][nt], Ahf[mt], &Bhf[nt >> 1][(nt & 1) * 2]);
#pragma unroll
            for (int mt = 0; mt < 2; mt++)
#pragma unroll
                for (int nt = 0; nt < 8; nt++)
                    mma_bf16(acc[mt][nt], Alf[mt], &Bhf[nt >> 1][(nt & 1) * 2]);
#pragma unroll
            for (int mt = 0; mt < 2; mt++)
#pragma unroll
                for (int nt = 0; nt < 8; nt++)
                    mma_bf16(acc[mt][nt], Ahf[mt], &Blf[nt >> 1][(nt & 1) * 2]);
        }
        __syncthreads();
    }

    // ---- fused per-channel stats from accumulators ----
    {
        float* bsm = (float*)(smem + BS_OFF);
        float* bqm = bsm + 128;
        if (tid < 128) { bsm[tid] = 0.f; bqm[tid] = 0.f; }
        __syncthreads();
#pragma unroll
        for (int nt = 0; nt < 8; nt++) {
            float se = 0.f, so = 0.f, qe = 0.f, qo = 0.f;
#pragma unroll
            for (int mt = 0; mt < 2; mt++) {
                float v0 = acc[mt][nt][0], v1 = acc[mt][nt][1];
                float v2 = acc[mt][nt][2], v3 = acc[mt][nt][3];
                se += v0 + v2; so += v1 + v3;
                qe = fmaf(v0, v0, fmaf(v2, v2, qe));
                qo = fmaf(v1, v1, fmaf(v3, v3, qo));
            }
#pragma unroll
            for (int m = 4; m <= 16; m <<= 1) {
                se += __shfl_xor_sync(0xffffffffu, se, m);
                so += __shfl_xor_sync(0xffffffffu, so, m);
                qe += __shfl_xor_sync(0xffffffffu, qe, m);
                qo += __shfl_xor_sync(0xffffffffu, qo, m);
            }
            if ((lane >> 2) == 0) {
                int ol = warp_n*64 + nt*8 + (lane & 3) * 2;
                atomicAdd(&bsm[ol],     se);
                atomicAdd(&bqm[ol],     qe);
                atomicAdd(&bsm[ol + 1], so);
                atomicAdd(&bqm[ol + 1], qo);
            }
        }
        __syncthreads();
        if (tid < 128) {
            if (MODE == 0) {
                atomicAdd(&g_sum1[o0 + tid], bsm[tid]);
                atomicAdd(&g_sq1[o0 + tid],  bqm[tid]);
            } else {
                atomicAdd(&g_sum2[o0 + tid], bsm[tid]);
                atomicAdd(&g_sq2[o0 + tid],  bqm[tid]);
            }
        }
    }

    if (MODE == 0) {
        // point-major y1[j][o]
#pragma unroll
        for (int mt = 0; mt < 2; mt++) {
            int j = j0 + warp_m*32 + mt*16 + (lane >> 2);
#pragma unroll
            for (int nt = 0; nt < 8; nt++) {
                int o = o0 + warp_n*64 + nt*8 + (lane & 3) * 2;
                *(float2*)&g_y1[(size_t)j * HCH + o]       = make_float2(acc[mt][nt][0], acc[mt][nt][1]);
                *(float2*)&g_y1[(size_t)(j + 8) * HCH + o] = make_float2(acc[mt][nt][2], acc[mt][nt][3]);
            }
        }
    } else {
        // channel-major out via smem transpose, 2 chunks of 64 o-rows
        int b = j0 >> 14, i0 = j0 & (NPTS - 1);
        float* tp = (float*)smem;                        // [64][132] = 33.8KB < BS_OFF
        for (int c = 0; c < 2; c++) {
            __syncthreads();
            if (warp_n == c) {
#pragma unroll
                for (int mt = 0; mt < 2; mt++) {
                    int jl = warp_m*32 + mt*16 + (lane >> 2);
#pragma unroll
                    for (int nt = 0; nt < 8; nt++) {
                        int ol = nt*8 + (lane & 3) * 2;
                        tp[ol * 132 + jl]           = acc[mt][nt][0];
                        tp[(ol + 1) * 132 + jl]     = acc[mt][nt][1];
                        tp[ol * 132 + jl + 8]       = acc[mt][nt][2];
                        tp[(ol + 1) * 132 + jl + 8] = acc[mt][nt][3];
                    }
                }
            }
            __syncthreads();
            int r = tid >> 2, part = tid & 3;
            int o = o0 + c*64 + r;
            float* dst = outp + ((size_t)(b * HCH + o)) * NPTS + i0 + part * 32;
            const float* srcr = tp + r * 132 + part * 32;
#pragma unroll
            for (int i = 0; i < 8; i++)
                *(float4*)(dst + i * 4) = make_float4(srcr[i*4+0], srcr[i*4+1], srcr[i*4+2], srcr[i*4+3]);
        }
    }
}

__global__ void finalize_kernel(const float* __restrict__ gamma,
                                const float* __restrict__ beta,
                                int which) {
    int o = threadIdx.x;
    const float invN = 1.f / (float)NTOT;
    float s  = (which == 1) ? g_sum1[o] : g_sum2[o];
    float q  = (which == 1) ? g_sq1[o]  : g_sq2[o];
    float mu  = s * invN;
    float var = q * invN - mu * mu;
    float sc  = gamma[o] * rsqrtf(var + 1e-5f);
    float sh  = fmaf(-mu, sc, beta[o]);
    if (which == 1) { g_scale1[o] = sc; g_shift1[o] = sh; }
    else            { g_scale2[o] = sc; g_shift2[o] = sh; }
}

// y1 -> relu(bn1) -> bf16 hi/lo (point-major [j][256])
__global__ void conv_act2_kernel() {
    size_t t = (size_t)blockIdx.x * 256 + threadIdx.x;   // float4 index
    int ob = (int)(t & 63) * 4;
    float4 v = ((const float4*)g_y1)[t];
    float x0 = fmaxf(0.f, fmaf(v.x, g_scale1[ob+0], g_shift1[ob+0]));
    float x1 = fmaxf(0.f, fmaf(v.y, g_scale1[ob+1], g_shift1[ob+1]));
    float x2 = fmaxf(0.f, fmaf(v.z, g_scale1[ob+2], g_shift1[ob+2]));
    float x3 = fmaxf(0.f, fmaf(v.w, g_scale1[ob+3], g_shift1[ob+3]));
    __nv_bfloat16 h0,l0,h1,l1,h2,l2,h3,l3;
    bsplit(x0,h0,l0); bsplit(x1,h1,l1); bsplit(x2,h2,l2); bsplit(x3,h3,l3);
    __nv_bfloat162 ha = __nv_bfloat162(h0,h1), hb = __nv_bfloat162(h2,h3);
    __nv_bfloat162 la = __nv_bfloat162(l0,l1), lb = __nv_bfloat162(l2,l3);
    uint2 uh = make_uint2(*(uint32_t*)&ha, *(uint32_t*)&hb);
    uint2 ul = make_uint2(*(uint32_t*)&la, *(uint32_t*)&lb);
    *(uint2*)(g_a2h + t * 4) = uh;
    *(uint2*)(g_a2l + t * 4) = ul;
}

// in-place BN2 + ReLU on channel-major output
__global__ void bnrelu_out_kernel(float* __restrict__ out) {
    size_t t = (size_t)blockIdx.x * 256 + threadIdx.x;
    int o = (int)((t >> 12) & 255);
    float sc = g_scale2[o], sh = g_shift2[o];
    float4 v = ((float4*)out)[t];
    v.x = fmaxf(0.f, fmaf(v.x, sc, sh));
    v.y = fmaxf(0.f, fmaf(v.y, sc, sh));
    v.z = fmaxf(0.f, fmaf(v.z, sc, sh));
    v.w = fmaxf(0.f, fmaf(v.w, sc, sh));
    ((float4*)out)[t] = v;
}

// ---------------- launch ----------------
extern "C" void kernel_launch(void* const* d_in, const int* in_sizes, int n_in,
                              void* d_out, int out_size) {
    const float* unknown       = (const float*)d_in[0];
    const float* known         = (const float*)d_in[1];
    const float* unknown_feats = (const float*)d_in[2];
    const float* known_feats   = (const float*)d_in[3];
    const float* W1            = (const float*)d_in[4];
    const float* gamma1        = (const float*)d_in[5];
    const float* beta1         = (const float*)d_in[6];
    const float* W2            = (const float*)d_in[7];
    const float* gamma2        = (const float*)d_in[8];
    const float* beta2         = (const float*)d_in[9];
    float* out = (float*)d_out;

    // created once on the first (non-captured) correctness call; reused in capture
    static cudaStream_t sB = nullptr;
    static cudaEvent_t evFork = nullptr, ev1 = nullptr, ev2 = nullptr;
    if (!sB) {
        cudaStreamCreateWithFlags(&sB, cudaStreamNonBlocking);
        cudaEventCreateWithFlags(&evFork, cudaEventDisableTiming);
        cudaEventCreateWithFlags(&ev1, cudaEventDisableTiming);
        cudaEventCreateWithFlags(&ev2, cudaEventDisableTiming);
    }

    cudaFuncSetAttribute(gemm_tc_kernel<K1, 0>, cudaFuncAttributeMaxDynamicSharedMemorySize, SM_TOT);
    cudaFuncSetAttribute(gemm_tc_kernel<HCH, 1>, cudaFuncAttributeMaxDynamicSharedMemorySize, SM_TOT);

    // ---- fork ----
    cudaEventRecord(evFork, 0);
    cudaStreamWaitEvent(sB, evFork, 0);

    // side stream: 3nn in two halves
    three_nn_partial_kernel<<<dim3(HALF/256, 4), 128, 0, sB>>>(unknown, known, 0);
    cudaEventRecord(ev1, sB);
    three_nn_partial_kernel<<<dim3(HALF/256, 4), 128, 0, sB>>>(unknown, known, HALF);
    cudaEventRecord(ev2, sB);

    // main: preps (hidden under 3nn h1)
    prep_kfw_kernel<<<dim3(128, 10, BB), dim3(32, 8)>>>(known_feats, W1, W2);
    prep_uf_kernel<<<dim3(NPTS/32, C1/32, BB), dim3(32, 8)>>>(unknown_feats);

    // main: interp h1 (under 3nn h2), then interp h2 after join
    cudaStreamWaitEvent(0, ev1, 0);
    interp_bf16_kernel<<<HALF/8, 256>>>(unknown, 0);
    cudaStreamWaitEvent(0, ev2, 0);
    interp_bf16_kernel<<<HALF/8, 256>>>(unknown, HALF);

    // serial tail (unchanged from R13)
    gemm_tc_kernel<K1, 0><<<dim3(NTOT/128, 2), 256, SM_TOT>>>(nullptr);
    finalize_kernel<<<1, 256>>>(gamma1, beta1, 1);
    conv_act2_kernel<<<(int)((size_t)NTOT*HCH/4/256), 256>>>();
    gemm_tc_kernel<HCH, 1><<<dim3(NTOT/128, 2), 256, SM_TOT>>>(out);
    finalize_kernel<<<1, 256>>>(gamma2, beta2, 2);
    bnrelu_out_kernel<<<(int)((size_t)BB*HCH*(NPTS/4)/256), 256>>>(out);
}

// round 17
// speedup vs baseline: 1.1451x; 1.1451x over previous
#include <cuda_runtime.h>
#include <cuda_bf16.h>
#include <math.h>
#include <cstdint>

#define BB   4
#define NPTS 16384
#define MPTS 4096
#define C1   128
#define C2   256
#define HCH  256
#define K1   384
#define NTOT (BB*NPTS)   // 65536

typedef unsigned long long u64;

// ---------------- mma / ldmatrix / cp.async helpers (sm_80+ baseline PTX) ----------------
__device__ __forceinline__ uint32_t smem_u32(const void* p) {
    uint32_t a;
    asm("{ .reg .u64 t; cvta.to.shared.u64 t, %1; cvt.u32.u64 %0, t; }" : "=r"(a) : "l"(p));
    return a;
}
__device__ __forceinline__ void ldsm4(uint32_t* r, uint32_t addr) {
    asm volatile("ldmatrix.sync.aligned.m8n8.x4.shared.b16 {%0,%1,%2,%3}, [%4];"
        : "=r"(r[0]), "=r"(r[1]), "=r"(r[2]), "=r"(r[3]) : "r"(addr));
}
__device__ __forceinline__ void mma_bf16(float* d, const uint32_t* a, const uint32_t* b) {
    asm volatile("mma.sync.aligned.m16n8k16.row.col.f32.bf16.bf16.f32 "
        "{%0,%1,%2,%3}, {%4,%5,%6,%7}, {%8,%9}, {%0,%1,%2,%3};"
        : "+f"(d[0]), "+f"(d[1]), "+f"(d[2]), "+f"(d[3])
        : "r"(a[0]), "r"(a[1]), "r"(a[2]), "r"(a[3]), "r"(b[0]), "r"(b[1]));
}
__device__ __forceinline__ void cp16(uint32_t saddr, const void* gaddr) {
    asm volatile("cp.async.cg.shared.global [%0], [%1], 16;" :: "r"(saddr), "l"(gaddr));
}
#define CP_COMMIT() asm volatile("cp.async.commit_group;" ::: "memory")
#define CP_WAIT(n)  asm volatile("cp.async.wait_group %0;" :: "n"(n) : "memory")

// smem stage layout: Ah, Al, Bh, Bl each 128 rows x 40 bf16 (80B rows)
#define MAT_BYTES (128*80)
#define OFF_AH 0
#define OFF_AL (MAT_BYTES)
#define OFF_BH (2*MAT_BYTES)
#define OFF_BL (3*MAT_BYTES)
#define STAGE  (4*MAT_BYTES)     // 40960
#define SM_TOT (2*STAGE)         // 81920
#define BS_OFF (SM_TOT - 2048)   // stats scratch; MODE1 transpose buffer (33.8KB) < BS_OFF

// ---------------- scratch (device globals) ----------------
__device__ float g_kfT[(size_t)BB*MPTS*C2];                         // 16.8 MB point-major known feats
__device__ __align__(16) __nv_bfloat16 g_ah[(size_t)NTOT*K1];       // A1 hi (point-major)
__device__ __align__(16) __nv_bfloat16 g_al[(size_t)NTOT*K1];       // A1 lo
__device__ __align__(16) __nv_bfloat16 g_w1h[HCH*K1], g_w1l[HCH*K1];
__device__ __align__(16) __nv_bfloat16 g_w2h[HCH*HCH], g_w2l[HCH*HCH];
__device__ __align__(16) __nv_bfloat16 g_a2h[(size_t)NTOT*HCH];     // A2 hi
__device__ __align__(16) __nv_bfloat16 g_a2l[(size_t)NTOT*HCH];
__device__ float g_y1[(size_t)NTOT*HCH];                            // gemm1 out, point-major
__device__ float g_ps[NTOT*12];
__device__ int   g_pi[NTOT*12];
__device__ float g_sum1[HCH], g_sq1[HCH], g_scale1[HCH], g_shift1[HCH];
__device__ float g_sum2[HCH], g_sq2[HCH], g_scale2[HCH], g_shift2[HCH];

__device__ __forceinline__ void bsplit(float x, __nv_bfloat16& h, __nv_bfloat16& l) {
    h = __float2bfloat16_rn(x);
    l = __float2bfloat16_rn(x - __bfloat162float(h));
}

// ---------------- prep A: kf transpose + W1/W2 split + zero stats ----------------
// grid (128, 10, BB), block (32, 8) = 256 threads
__global__ void prep_kfw_kernel(const float* __restrict__ kf,
                                const float* __restrict__ W1,
                                const float* __restrict__ W2) {
    __shared__ float tile[32][33];
    int tx = threadIdx.x, ty = threadIdx.y;
    int b = blockIdx.z, y = blockIdx.y, x = blockIdx.x;
    int tid = ty * 32 + tx;

    if (y < 8) {                                     // kf [b][c][p] -> g_kfT [b][p][c]
        int p0 = x * 32, c0 = y * 32;
        const float* src = kf + (size_t)b * C2 * MPTS;
        float* dst = g_kfT + (size_t)b * MPTS * C2;
#pragma unroll
        for (int r = 0; r < 32; r += 8)
            tile[ty + r][tx] = src[(size_t)(c0 + ty + r) * MPTS + p0 + tx];
        __syncthreads();
#pragma unroll
        for (int r = 0; r < 32; r += 8)
            dst[(size_t)(p0 + ty + r) * C2 + c0 + tx] = tile[tx][ty + r];
    } else if (y == 8) {                             // W1 split: 128 blocks x 3 chunks
        if (b != 0) return;
#pragma unroll
        for (int c = 0; c < 3; c++) {
            int i = (x * 3 + c) * 256 + tid;         // < 98304 = HCH*K1
            __nv_bfloat16 h, l; bsplit(W1[i], h, l);
            g_w1h[i] = h; g_w1l[i] = l;
        }
    } else {                                         // y == 9: W2 split + stats
        if (b != 0) return;
        if (x < 64) {
#pragma unroll
            for (int c = 0; c < 4; c++) {
                int i = (x * 4 + c) * 256 + tid;     // < 65536 = HCH*HCH
                __nv_bfloat16 h, l; bsplit(W2[i], h, l);
                g_w2h[i] = h; g_w2l[i] = l;
            }
        } else if (x == 64) {
            g_sum1[tid] = 0.f; g_sq1[tid] = 0.f;
            g_sum2[tid] = 0.f; g_sq2[tid] = 0.f;
        }
    }
}

// ---------------- prep B: uf transpose + bf16 split -> g_ah/g_al[j][256+c] ----------------
__global__ void prep_uf_kernel(const float* __restrict__ uf) {
    __shared__ float tile[32][33];
    int tx = threadIdx.x, ty = threadIdx.y;
    int b = blockIdx.z;
    int c0 = blockIdx.y * 32, i0 = blockIdx.x * 32;
    const float* src = uf + (size_t)b * C1 * NPTS;
#pragma unroll
    for (int r = 0; r < 32; r += 8)
        tile[ty + r][tx] = src[(size_t)(c0 + ty + r) * NPTS + i0 + tx];
    __syncthreads();
#pragma unroll
    for (int r = 0; r < 32; r += 8) {
        int j = b * NPTS + i0 + ty + r;
        float v = tile[tx][ty + r];
        __nv_bfloat16 h, l; bsplit(v, h, l);
        g_ah[(size_t)j * K1 + C2 + c0 + tx] = h;
        g_al[(size_t)j * K1 + C2 + c0 + tx] = l;
    }
}

// ---------------- split-m 3-NN partials, 2 points per thread (R8 version) ----------------
__global__ void __launch_bounds__(128) three_nn_partial_kernel(
        const float* __restrict__ unknown, const float* __restrict__ known) {
    int tid = threadIdx.x;
    int gA = blockIdx.x * 256 + tid;
    int gB = gA + 128;
    int t = blockIdx.y;
    int b = gA >> 14;

    __shared__ float4 sk[1024];
    const float* kb = known + ((size_t)b * MPTS + t * 1024) * 3;
    for (int q = tid; q < 1024; q += 128) {
        float x = kb[q*3+0], y = kb[q*3+1], z = kb[q*3+2];
        sk[q] = make_float4(x, y, z, x*x + y*y + z*z);
    }
    __syncthreads();

    float ax = unknown[gA*3+0], ay = unknown[gA*3+1], az = unknown[gA*3+2];
    float bx = unknown[gB*3+0], by = unknown[gB*3+1], bz = unknown[gB*3+2];
    float caA = -2.f*ax, cbA = -2.f*ay, ccA = -2.f*az;
    float caB = -2.f*bx, cbB = -2.f*by, ccB = -2.f*bz;

    float a0 = 3.4e38f, a1 = 3.4e38f, a2 = 3.4e38f;
    float b0 = 3.4e38f, b1 = 3.4e38f, b2 = 3.4e38f;
    int   ia0 = 0, ia1 = 0, ia2 = 0, ib0 = 0, ib1 = 0, ib2 = 0;

#pragma unroll 4
    for (int jj = 0; jj < 1024; jj++) {
        float4 k4 = sk[jj];
        float s = fmaf(k4.x, caA, fmaf(k4.y, cbA, fmaf(k4.z, ccA, k4.w)));
        float u = fmaf(k4.x, caB, fmaf(k4.y, cbB, fmaf(k4.z, ccB, k4.w)));
        if (s < a2) {
            if (s < a1) {
                a2 = a1; ia2 = ia1;
                if (s < a0) { a1 = a0; ia1 = ia0; a0 = s; ia0 = jj; }
                else        { a1 = s;  ia1 = jj; }
            } else { a2 = s; ia2 = jj; }
        }
        if (u < b2) {
            if (u < b1) {
                b2 = b1; ib2 = ib1;
                if (u < b0) { b1 = b0; ib1 = ib0; b0 = u; ib0 = jj; }
                else        { b1 = u;  ib1 = jj; }
            } else { b2 = u; ib2 = jj; }
        }
    }
    int base = t * 1024;
    int oA = gA * 12 + t * 3, oB = gB * 12 + t * 3;
    g_ps[oA+0] = a0; g_ps[oA+1] = a1; g_ps[oA+2] = a2;
    g_pi[oA+0] = base + ia0; g_pi[oA+1] = base + ia1; g_pi[oA+2] = base + ia2;
    g_ps[oB+0] = b0; g_ps[oB+1] = b1; g_ps[oB+2] = b2;
    g_pi[oB+0] = base + ib0; g_pi[oB+1] = base + ib1; g_pi[oB+2] = base + ib2;
}

// ---------------- merge + gather + interpolate -> A[j][0..255] bf16 hi/lo ----------------
__global__ void __launch_bounds__(256) interp_bf16_kernel(const float* __restrict__ unknown) {
    int warp = threadIdx.x >> 5, lane = threadIdx.x & 31;
    int g = blockIdx.x * 8 + warp;
    int b = g >> 14;

    float sl = (lane < 12) ? g_ps[g*12 + lane] : 3.4e38f;
    int   il = (lane < 12) ? g_pi[g*12 + lane] : 0;
    float s0 = 3.4e38f, s1 = 3.4e38f, s2 = 3.4e38f;
    int   i0 = 0, i1 = 0, i2 = 0;
#pragma unroll
    for (int j = 0; j < 12; j++) {
        float sj = __shfl_sync(0xffffffffu, sl, j);
        int   ij = __shfl_sync(0xffffffffu, il, j);
        if (sj < s2) {
            if (sj < s1) {
                s2 = s1; i2 = i1;
                if (sj < s0) { s1 = s0; i1 = i0; s0 = sj; i0 = ij; }
                else         { s1 = sj; i1 = ij; }
            } else { s2 = sj; i2 = ij; }
        }
    }
    float ux = unknown[g*3+0], uy = unknown[g*3+1], uz = unknown[g*3+2];
    float u2 = ux*ux + uy*uy + uz*uz;
    float d0 = s0 + u2, d1 = s1 + u2, d2 = s2 + u2;
    float r0 = 1.f / (d0 + 1e-8f), r1 = 1.f / (d1 + 1e-8f), r2 = 1.f / (d2 + 1e-8f);
    float rs = r0 + r1 + r2;
    float w0 = r0 / rs, w1 = r1 / rs, w2 = r2 / rs;

    const float4* f0 = (const float4*)&g_kfT[((size_t)(b*MPTS) + i0) * C2];
    const float4* f1 = (const float4*)&g_kfT[((size_t)(b*MPTS) + i1) * C2];
    const float4* f2 = (const float4*)&g_kfT[((size_t)(b*MPTS) + i2) * C2];

    float vals[8];
#pragma unroll
    for (int h = 0; h < 2; h++) {
        int v = lane*2 + h;
        float4 a = f0[v], c = f1[v], d = f2[v];
        vals[h*4+0] = fmaf(w0, a.x, fmaf(w1, c.x, w2 * d.x));
        vals[h*4+1] = fmaf(w0, a.y, fmaf(w1, c.y, w2 * d.y));
        vals[h*4+2] = fmaf(w0, a.z, fmaf(w1, c.z, w2 * d.z));
        vals[h*4+3] = fmaf(w0, a.w, fmaf(w1, c.w, w2 * d.w));
    }
    uint4 uh, ul;
    uint32_t* ph = (uint32_t*)&uh;
    uint32_t* pl = (uint32_t*)&ul;
#pragma unroll
    for (int q = 0; q < 4; q++) {
        __nv_bfloat16 h0, l0, h1, l1;
        bsplit(vals[q*2+0], h0, l0);
        bsplit(vals[q*2+1], h1, l1);
        __nv_bfloat162 hh = __nv_bfloat162(h0, h1);
        __nv_bfloat162 ll = __nv_bfloat162(l0, l1);
        ph[q] = *(uint32_t*)&hh;
        pl[q] = *(uint32_t*)&ll;
    }
    *(uint4*)(g_ah + (size_t)g * K1 + lane * 8) = uh;
    *(uint4*)(g_al + (size_t)g * K1 + lane * 8) = ul;
}

// ---------------- bf16x3 GEMM via mma.sync (R8 version: separate Blf, lb(256,2), fused stats) ----------------
template<int KD, int MODE>
__global__ void __launch_bounds__(256, 2) gemm_tc_kernel(float* __restrict__ outp) {
    extern __shared__ __align__(16) char smem[];
    const uint32_t su = smem_u32(smem);
    const int tid = threadIdx.x, lane = tid & 31, warp = tid >> 5;
    const int warp_m = warp >> 1, warp_n = warp & 1;
    const int j0 = blockIdx.x * 128, o0 = blockIdx.y * 128;

    const __nv_bfloat16 *Ah, *Al, *Bh, *Bl;
    if (MODE == 0) { Ah = g_ah;  Al = g_al;  Bh = g_w1h; Bl = g_w1l; }
    else           { Ah = g_a2h; Al = g_a2l; Bh = g_w2h; Bl = g_w2l; }

    const int NCH = KD / 32;
    int lrow0 = tid >> 2, lcg = (tid & 3) * 8;

    uint32_t a_off[2], b_off[4];
#pragma unroll
    for (int mt = 0; mt < 2; mt++)
        a_off[mt] = (uint32_t)((warp_m*32 + mt*16 + (lane & 15)) * 80 + ((lane >> 4) << 3) * 2);
#pragma unroll
    for (int np = 0; np < 4; np++)
        b_off[np] = (uint32_t)((warp_n*64 + np*16 + (lane & 7) + ((lane >> 4) << 3)) * 80
                               + (((lane >> 3) & 1) << 3) * 2);

    float acc[2][8][4];
#pragma unroll
    for (int mt = 0; mt < 2; mt++)
#pragma unroll
        for (int nt = 0; nt < 8; nt++)
#pragma unroll
            for (int q = 0; q < 4; q++) acc[mt][nt][q] = 0.f;

    // prefetch chunk 0
    {
        uint32_t sb = su;
#pragma unroll
        for (int t = 0; t < 2; t++) {
            int row = lrow0 + t * 64;
            uint32_t so = (uint32_t)(row * 80 + lcg * 2);
            cp16(sb + OFF_AH + so, Ah + (size_t)(j0 + row) * KD + lcg);
            cp16(sb + OFF_AL + so, Al + (size_t)(j0 + row) * KD + lcg);
            cp16(sb + OFF_BH + so, Bh + (size_t)(o0 + row) * KD + lcg);
            cp16(sb + OFF_BL + so, Bl + (size_t)(o0 + row) * KD + lcg);
        }
        CP_COMMIT();
    }

    for (int ch = 0; ch < NCH; ch++) {
        if (ch + 1 < NCH) {
            int kc = (ch + 1) * 32;
            uint32_t sb = su + ((ch + 1) & 1) * STAGE;
#pragma unroll
            for (int t = 0; t < 2; t++) {
                int row = lrow0 + t * 64;
                uint32_t so = (uint32_t)(row * 80 + lcg * 2);
                cp16(sb + OFF_AH + so, Ah + (size_t)(j0 + row) * KD + kc + lcg);
                cp16(sb + OFF_AL + so, Al + (size_t)(j0 + row) * KD + kc + lcg);
                cp16(sb + OFF_BH + so, Bh + (size_t)(o0 + row) * KD + kc + lcg);
                cp16(sb + OFF_BL + so, Bl + (size_t)(o0 + row) * KD + kc + lcg);
            }
            CP_COMMIT();
            CP_WAIT(1);
        } else {
            CP_WAIT(0);
        }
        __syncthreads();

        uint32_t sb = su + (ch & 1) * STAGE;
#pragma unroll
        for (int ks = 0; ks < 32; ks += 16) {
            uint32_t Ahf[2][4], Alf[2][4], Bhf[4][4], Blf[4][4];
#pragma unroll
            for (int mt = 0; mt < 2; mt++) {
                ldsm4(Ahf[mt], sb + OFF_AH + a_off[mt] + ks*2);
                ldsm4(Alf[mt], sb + OFF_AL + a_off[mt] + ks*2);
            }
#pragma unroll
            for (int np = 0; np < 4; np++)
                ldsm4(Bhf[np], sb + OFF_BH + b_off[np] + ks*2);
#pragma unroll
            for (int np = 0; np < 4; np++)
                ldsm4(Blf[np], sb + OFF_BL + b_off[np] + ks*2);
#pragma unroll
            for (int mt = 0; mt < 2; mt++)
#pragma unroll
                for (int nt = 0; nt < 8; nt++)
                    mma_bf16(acc[mt][nt], Ahf[mt], &Bhf[nt >> 1][(nt & 1) * 2]);
#pragma unroll
            for (int mt = 0; mt < 2; mt++)
#pragma unroll
                for (int nt = 0; nt < 8; nt++)
                    mma_bf16(acc[mt][nt], Alf[mt], &Bhf[nt >> 1][(nt & 1) * 2]);
#pragma unroll
            for (int mt = 0; mt < 2; mt++)
#pragma unroll
                for (int nt = 0; nt < 8; nt++)
                    mma_bf16(acc[mt][nt], Ahf[mt], &Blf[nt >> 1][(nt & 1) * 2]);
        }
        __syncthreads();
    }

    // ---- fused per-channel stats from accumulators ----
    {
        float* bsm = (float*)(smem + BS_OFF);
        float* bqm = bsm + 128;
        if (tid < 128) { bsm[tid] = 0.f; bqm[tid] = 0.f; }
        __syncthreads();
#pragma unroll
        for (int nt = 0; nt < 8; nt++) {
            float se = 0.f, so = 0.f, qe = 0.f, qo = 0.f;
#pragma unroll
            for (int mt = 0; mt < 2; mt++) {
                float v0 = acc[mt][nt][0], v1 = acc[mt][nt][1];
                float v2 = acc[mt][nt][2], v3 = acc[mt][nt][3];
                se += v0 + v2; so += v1 + v3;
                qe = fmaf(v0, v0, fmaf(v2, v2, qe));
                qo = fmaf(v1, v1, fmaf(v3, v3, qo));
            }
#pragma unroll
            for (int m = 4; m <= 16; m <<= 1) {
                se += __shfl_xor_sync(0xffffffffu, se, m);
                so += __shfl_xor_sync(0xffffffffu, so, m);
                qe += __shfl_xor_sync(0xffffffffu, qe, m);
                qo += __shfl_xor_sync(0xffffffffu, qo, m);
            }
            if ((lane >> 2) == 0) {
                int ol = warp_n*64 + nt*8 + (lane & 3) * 2;
                atomicAdd(&bsm[ol],     se);
                atomicAdd(&bqm[ol],     qe);
                atomicAdd(&bsm[ol + 1], so);
                atomicAdd(&bqm[ol + 1], qo);
            }
        }
        __syncthreads();
        if (tid < 128) {
            if (MODE == 0) {
                atomicAdd(&g_sum1[o0 + tid], bsm[tid]);
                atomicAdd(&g_sq1[o0 + tid],  bqm[tid]);
            } else {
                atomicAdd(&g_sum2[o0 + tid], bsm[tid]);
                atomicAdd(&g_sq2[o0 + tid],  bqm[tid]);
            }
        }
    }

    if (MODE == 0) {
        // point-major y1[j][o]
#pragma unroll
        for (int mt = 0; mt < 2; mt++) {
            int j = j0 + warp_m*32 + mt*16 + (lane >> 2);
#pragma unroll
            for (int nt = 0; nt < 8; nt++) {
                int o = o0 + warp_n*64 + nt*8 + (lane & 3) * 2;
                *(float2*)&g_y1[(size_t)j * HCH + o]       = make_float2(acc[mt][nt][0], acc[mt][nt][1]);
                *(float2*)&g_y1[(size_t)(j + 8) * HCH + o] = make_float2(acc[mt][nt][2], acc[mt][nt][3]);
            }
        }
    } else {
        // channel-major out via smem transpose, 2 chunks of 64 o-rows
        int b = j0 >> 14, i0 = j0 & (NPTS - 1);
        float* tp = (float*)smem;                        // [64][132] = 33.8KB < BS_OFF
        for (int c = 0; c < 2; c++) {
            __syncthreads();
            if (warp_n == c) {
#pragma unroll
                for (int mt = 0; mt < 2; mt++) {
                    int jl = warp_m*32 + mt*16 + (lane >> 2);
#pragma unroll
                    for (int nt = 0; nt < 8; nt++) {
                        int ol = nt*8 + (lane & 3) * 2;
                        tp[ol * 132 + jl]           = acc[mt][nt][0];
                        tp[(ol + 1) * 132 + jl]     = acc[mt][nt][1];
                        tp[ol * 132 + jl + 8]       = acc[mt][nt][2];
                        tp[(ol + 1) * 132 + jl + 8] = acc[mt][nt][3];
                    }
                }
            }
            __syncthreads();
            int r = tid >> 2, part = tid & 3;
            int o = o0 + c*64 + r;
            float* dst = outp + ((size_t)(b * HCH + o)) * NPTS + i0 + part * 32;
            const float* srcr = tp + r * 132 + part * 32;
#pragma unroll
            for (int i = 0; i < 8; i++)
                *(float4*)(dst + i * 4) = make_float4(srcr[i*4+0], srcr[i*4+1], srcr[i*4+2], srcr[i*4+3]);
        }
    }
}

__global__ void finalize_kernel(const float* __restrict__ gamma,
                                const float* __restrict__ beta,
                                int which) {
    int o = threadIdx.x;
    const float invN = 1.f / (float)NTOT;
    float s  = (which == 1) ? g_sum1[o] : g_sum2[o];
    float q  = (which == 1) ? g_sq1[o]  : g_sq2[o];
    float mu  = s * invN;
    float var = q * invN - mu * mu;
    float sc  = gamma[o] * rsqrtf(var + 1e-5f);
    float sh  = fmaf(-mu, sc, beta[o]);
    if (which == 1) { g_scale1[o] = sc; g_shift1[o] = sh; }
    else            { g_scale2[o] = sc; g_shift2[o] = sh; }
}

// y1 -> relu(bn1) -> bf16 hi/lo (point-major [j][256])
__global__ void conv_act2_kernel() {
    size_t t = (size_t)blockIdx.x * 256 + threadIdx.x;   // float4 index
    int ob = (int)(t & 63) * 4;
    float4 v = ((const float4*)g_y1)[t];
    float x0 = fmaxf(0.f, fmaf(v.x, g_scale1[ob+0], g_shift1[ob+0]));
    float x1 = fmaxf(0.f, fmaf(v.y, g_scale1[ob+1], g_shift1[ob+1]));
    float x2 = fmaxf(0.f, fmaf(v.z, g_scale1[ob+2], g_shift1[ob+2]));
    float x3 = fmaxf(0.f, fmaf(v.w, g_scale1[ob+3], g_shift1[ob+3]));
    __nv_bfloat16 h0,l0,h1,l1,h2,l2,h3,l3;
    bsplit(x0,h0,l0); bsplit(x1,h1,l1); bsplit(x2,h2,l2); bsplit(x3,h3,l3);
    __nv_bfloat162 ha = __nv_bfloat162(h0,h1), hb = __nv_bfloat162(h2,h3);
    __nv_bfloat162 la = __nv_bfloat162(l0,l1), lb = __nv_bfloat162(l2,l3);
    uint2 uh = make_uint2(*(uint32_t*)&ha, *(uint32_t*)&hb);
    uint2 ul = make_uint2(*(uint32_t*)&la, *(uint32_t*)&lb);
    *(uint2*)(g_a2h + t * 4) = uh;
    *(uint2*)(g_a2l + t * 4) = ul;
}

// in-place BN2 + ReLU on channel-major output
__global__ void bnrelu_out_kernel(float* __restrict__ out) {
    size_t t = (size_t)blockIdx.x * 256 + threadIdx.x;
    int o = (int)((t >> 12) & 255);
    float sc = g_scale2[o], sh = g_shift2[o];
    float4 v = ((float4*)out)[t];
    v.x = fmaxf(0.f, fmaf(v.x, sc, sh));
    v.y = fmaxf(0.f, fmaf(v.y, sc, sh));
    v.z = fmaxf(0.f, fmaf(v.z, sc, sh));
    v.w = fmaxf(0.f, fmaf(v.w, sc, sh));
    ((float4*)out)[t] = v;
}

// ---------------- launch ----------------
extern "C" void kernel_launch(void* const* d_in, const int* in_sizes, int n_in,
                              void* d_out, int out_size) {
    const float* unknown       = (const float*)d_in[0];
    const float* known         = (const float*)d_in[1];
    const float* unknown_feats = (const float*)d_in[2];
    const float* known_feats   = (const float*)d_in[3];
    const float* W1            = (const float*)d_in[4];
    const float* gamma1        = (const float*)d_in[5];
    const float* beta1         = (const float*)d_in[6];
    const float* W2            = (const float*)d_in[7];
    const float* gamma2        = (const float*)d_in[8];
    const float* beta2         = (const float*)d_in[9];
    float* out = (float*)d_out;

    // created once (outside any graph capture on first, non-captured call); reused after
    static cudaStream_t sB = nullptr;
    static cudaEvent_t evFork = nullptr, evJoin = nullptr;
    if (!sB) {
        cudaStreamCreateWithFlags(&sB, cudaStreamNonBlocking);
        cudaEventCreateWithFlags(&evFork, cudaEventDisableTiming);
        cudaEventCreateWithFlags(&evJoin, cudaEventDisableTiming);
    }

    cudaFuncSetAttribute(gemm_tc_kernel<K1, 0>, cudaFuncAttributeMaxDynamicSharedMemorySize, SM_TOT);
    cudaFuncSetAttribute(gemm_tc_kernel<HCH, 1>, cudaFuncAttributeMaxDynamicSharedMemorySize, SM_TOT);

    // fork: three_nn (compute-bound) on side stream, preps (memory-bound) on main
    cudaEventRecord(evFork, 0);
    cudaStreamWaitEvent(sB, evFork, 0);
    three_nn_partial_kernel<<<dim3(NTOT/256, 4), 128, 0, sB>>>(unknown, known);      // 1
    cudaEventRecord(evJoin, sB);

    prep_kfw_kernel<<<dim3(128, 10, BB), dim3(32, 8)>>>(known_feats, W1, W2);        // 2
    prep_uf_kernel<<<dim3(NPTS/32, C1/32, BB), dim3(32, 8)>>>(unknown_feats);        // 3

    cudaStreamWaitEvent(0, evJoin, 0);     // join before interp
    interp_bf16_kernel<<<NTOT/8, 256>>>(unknown);                                    // 4 (ncu)
    gemm_tc_kernel<K1, 0><<<dim3(NTOT/128, 2), 256, SM_TOT>>>(nullptr);
    finalize_kernel<<<1, 256>>>(gamma1, beta1, 1);
    conv_act2_kernel<<<(int)((size_t)NTOT*HCH/4/256), 256>>>();
    gemm_tc_kernel<HCH, 1><<<dim3(NTOT/128, 2), 256, SM_TOT>>>(out);
    finalize_kernel<<<1, 256>>>(gamma2, beta2, 2);
    bnrelu_out_kernel<<<(int)((size_t)BB*HCH*(NPTS/4)/256), 256>>>(out);
}